// round 16
// baseline (speedup 1.0000x reference)
#include <cuda_runtime.h>
#include <cuda_fp16.h>
#include <cstdint>

// Problem dims (fixed):
// features [3200, 4096] f32, phrases [3200, 15, 1024] f32,
// W [1024, 4096] f32, b [1024] f32, phrase_lengths [3200] i32
// out [3200, 2048] f32 : cols 0..1023 = relu(A@W^T + b), cols 1024..2047 = phrase mean
#define M_DIM 3200
#define N_DIM 1024
#define K_DIM 4096
#define OUT_STRIDE 2048
#define L_DIM 15
#define D_DIM 1024

// ---------------- device-global buffers ----------------
__device__ __half g_Ah[(size_t)M_DIM * K_DIM];
__device__ __half g_Wh[(size_t)N_DIM * K_DIM];

// ---------------- helpers ----------------
__device__ __forceinline__ uint32_t smem_to_u32(const void* p) {
    uint32_t a;
    asm("{ .reg .u64 t; cvta.to.shared.u64 t, %1; cvt.u32.u64 %0, t; }" : "=r"(a) : "l"(p));
    return a;
}
__device__ __forceinline__ void cp16(uint32_t dst, const void* src) {
    asm volatile("cp.async.cg.shared.global [%0], [%1], 16;" :: "r"(dst), "l"(src) : "memory");
}
#define CP_COMMIT() asm volatile("cp.async.commit_group;" ::: "memory")
#define CP_WAIT1()  asm volatile("cp.async.wait_group 1;" ::: "memory")
#define CP_WAIT0()  asm volatile("cp.async.wait_group 0;" ::: "memory")

__device__ __forceinline__ void ldm_x4(uint32_t* r, uint32_t addr) {
    asm volatile("ldmatrix.sync.aligned.m8n8.x4.shared.b16 {%0,%1,%2,%3}, [%4];"
                 : "=r"(r[0]), "=r"(r[1]), "=r"(r[2]), "=r"(r[3]) : "r"(addr));
}
__device__ __forceinline__ void mma16816(float* c, const uint32_t* a, uint32_t b0, uint32_t b1) {
    asm volatile(
        "mma.sync.aligned.m16n8k16.row.col.f32.f16.f16.f32 "
        "{%0,%1,%2,%3}, {%4,%5,%6,%7}, {%8,%9}, {%0,%1,%2,%3};"
        : "+f"(c[0]), "+f"(c[1]), "+f"(c[2]), "+f"(c[3])
        : "r"(a[0]), "r"(a[1]), "r"(a[2]), "r"(a[3]), "r"(b0), "r"(b1));
}

// ---------------- convert prepass: fp32 -> fp16, 16 floats/thread ----------------
#define A_N16 (M_DIM * K_DIM / 16)
#define W_N16 (N_DIM * K_DIM / 16)
__global__ __launch_bounds__(256)
void convert_kernel(const float* __restrict__ A, const float* __restrict__ W) {
    const float4* a4 = reinterpret_cast<const float4*>(A);
    const float4* w4 = reinterpret_cast<const float4*>(W);
    uint4* Ao = reinterpret_cast<uint4*>(g_Ah);
    uint4* Wo = reinterpret_cast<uint4*>(g_Wh);
    for (int i = blockIdx.x * blockDim.x + threadIdx.x; i < A_N16 + W_N16;
         i += gridDim.x * blockDim.x) {
        const float4* src;
        uint4* dst;
        int j;
        if (i < A_N16) { src = a4; dst = Ao; j = i; }
        else           { src = w4; dst = Wo; j = i - A_N16; }
#pragma unroll
        for (int h = 0; h < 2; h++) {
            float4 v0 = src[4 * j + 2 * h];
            float4 v1 = src[4 * j + 2 * h + 1];
            __half2 hh[4];
            hh[0] = __floats2half2_rn(v0.x, v0.y);
            hh[1] = __floats2half2_rn(v0.z, v0.w);
            hh[2] = __floats2half2_rn(v1.x, v1.y);
            hh[3] = __floats2half2_rn(v1.z, v1.w);
            dst[2 * j + h] = *reinterpret_cast<const uint4*>(hh);
        }
    }
}

// ---------------- fp16 mma.sync GEMM, full K, fused bias+relu ----------------
// BM=128, BN=64, BK=32. 4 warps (128 threads), warp tile 32x64.
// NSTAGE=3 cp.async pipeline, prefetch distance 2 (steady WAIT1, tail WAIT0),
// single register fragment buffer. 4 CTAs/SM, 400 CTAs = 1 wave, 16 warps/SM.
#define BK 32
#define NC (K_DIM / BK)          // 128
#define ROW_B 80
#define A_TILE (128 * ROW_B)     // 10240
#define B_TILE (64 * ROW_B)      // 5120
#define STAGE_BYTES (A_TILE + B_TILE)           // 15360
#define NSTAGE 3
#define GEMM_SMEM (NSTAGE * STAGE_BYTES)        // 46080

struct Frags {
    uint32_t a[2][4];
    uint32_t b[4][4];
};

__global__ __launch_bounds__(128, 4)
void gemm_mma_kernel(const float* __restrict__ bias, float* __restrict__ out) {
    extern __shared__ char smem[];
    const uint32_t sbase = smem_to_u32(smem);
    const int tid = threadIdx.x;
    const int lane = tid & 31;
    const int wm = tid >> 5;            // 0..3, warp rows wm*32..+31
    const int bm = blockIdx.y * 128;
    const int bn = blockIdx.x * 64;

    const int l_row = tid >> 2;         // 0..31
    const int l_c   = tid & 3;

    auto load_chunk = [&](int chunk, int stage) {
        const int kt = chunk * BK;
        const uint32_t sb = sbase + (uint32_t)stage * STAGE_BYTES;
#pragma unroll
        for (int j = 0; j < 4; j++) {   // A: 128 rows
            const int row = l_row + j * 32;
            const uint32_t off = (uint32_t)(row * ROW_B + l_c * 16);
            cp16(sb + off, g_Ah + (size_t)(bm + row) * K_DIM + kt + l_c * 8);
        }
#pragma unroll
        for (int j = 0; j < 2; j++) {   // W: 64 rows
            const int row = l_row + j * 32;
            const uint32_t off = (uint32_t)(row * ROW_B + l_c * 16);
            cp16(sb + A_TILE + off, g_Wh + (size_t)(bn + row) * K_DIM + kt + l_c * 8);
        }
    };

    float acc[2][8][4];
#pragma unroll
    for (int t = 0; t < 2; t++)
#pragma unroll
        for (int j = 0; j < 8; j++)
#pragma unroll
            for (int q = 0; q < 4; q++) acc[t][j][q] = 0.0f;

    const uint32_t a_lrow = (uint32_t)(wm * 32 + (lane & 15));
    const uint32_t a_lkof = (uint32_t)((lane >> 4) << 4);
    const int grp = lane >> 3;
    const uint32_t b_ln   = (uint32_t)(((grp >> 1) << 3) + (lane & 7));
    const uint32_t b_lkof = (uint32_t)((grp & 1) << 4);

    Frags fr;

    auto ldsm_all = [&](int stage, int ks) {
        const uint32_t sb = sbase + (uint32_t)stage * STAGE_BYTES;
        const uint32_t akoff = (uint32_t)(ks * 32) + a_lkof;
        const uint32_t bkoff = (uint32_t)(ks * 32) + b_lkof;
#pragma unroll
        for (int t = 0; t < 2; t++)
            ldm_x4(fr.a[t], sb + (a_lrow + t * 16) * ROW_B + akoff);
#pragma unroll
        for (int p = 0; p < 4; p++)
            ldm_x4(fr.b[p], sb + A_TILE + (b_ln + p * 16) * ROW_B + bkoff);
    };

    auto mma_all = [&]() {
#pragma unroll
        for (int t = 0; t < 2; t++)
#pragma unroll
            for (int j = 0; j < 8; j++) {
                const int p = j >> 1;
                const int q = (j & 1) * 2;
                mma16816(acc[t][j], fr.a[t], fr.b[p][q], fr.b[p][q + 1]);
            }
    };

    // prologue: fill 2 of 3 stages
    load_chunk(0, 0); CP_COMMIT();
    load_chunk(1, 1); CP_COMMIT();

    for (int c = 0; c < NC; c++) {
        // Chunk c must be COMPLETE. Steady state: outstanding {c, c+1} ->
        // WAIT1 completes c. Tail (c is last; c+1 never committed): only {c}
        // outstanding -> WAIT1 would NOT wait for it; drain fully.
        if (c + 1 < NC) { CP_WAIT1(); } else { CP_WAIT0(); }
        __syncthreads();   // all warps finished iter c-1 (stage (c+2)%3 reads)
        if (c + 2 < NC) { load_chunk(c + 2, (c + 2) % NSTAGE); CP_COMMIT(); }

        const int stage = c % NSTAGE;
        ldsm_all(stage, 0);
        mma_all();
        ldsm_all(stage, 1);
        mma_all();
    }

    // epilogue: bias + relu, direct store
    const int g  = lane >> 2;
    const int tg = lane & 3;
#pragma unroll
    for (int t = 0; t < 2; t++) {
#pragma unroll
        for (int j = 0; j < 8; j++) {
            const int col = j * 8 + tg * 2;
            const float b0 = bias[bn + col];
            const float b1 = bias[bn + col + 1];
            const int row0 = bm + wm * 32 + t * 16 + g;
            float2 v0, v1;
            v0.x = fmaxf(acc[t][j][0] + b0, 0.0f);
            v0.y = fmaxf(acc[t][j][1] + b1, 0.0f);
            v1.x = fmaxf(acc[t][j][2] + b0, 0.0f);
            v1.y = fmaxf(acc[t][j][3] + b1, 0.0f);
            *reinterpret_cast<float2*>(out + (size_t)row0 * OUT_STRIDE + bn + col) = v0;
            *reinterpret_cast<float2*>(out + (size_t)(row0 + 8) * OUT_STRIDE + bn + col) = v1;
        }
    }
}

// ---------------- phrase mean: out[:, 1024:2048] ----------------
__global__ __launch_bounds__(256)
void phrase_mean_kernel(const float* __restrict__ phrases,
                        const int* __restrict__ lens,
                        float* __restrict__ out) {
    const int row = blockIdx.x;
    const int d4 = threadIdx.x;
    const float4* p = reinterpret_cast<const float4*>(phrases + (size_t)row * L_DIM * D_DIM) + d4;
    float4 s = make_float4(0.f, 0.f, 0.f, 0.f);
#pragma unroll
    for (int l = 0; l < L_DIM; l++) {
        float4 v = p[l * (D_DIM / 4)];
        s.x += v.x; s.y += v.y; s.z += v.z; s.w += v.w;
    }
    const float inv = 1.0f / (float)lens[row];
    s.x *= inv; s.y *= inv; s.z *= inv; s.w *= inv;
    reinterpret_cast<float4*>(out + (size_t)row * OUT_STRIDE + D_DIM)[d4] = s;
}

// ---------------- launch ----------------
extern "C" void kernel_launch(void* const* d_in, const int* in_sizes, int n_in,
                              void* d_out, int out_size) {
    const float* features = (const float*)d_in[0];
    const float* phrases  = (const float*)d_in[1];
    const float* W        = (const float*)d_in[2];
    const float* bias     = (const float*)d_in[3];
    const int*   lens     = (const int*)d_in[4];
    float* out = (float*)d_out;

    static cudaStream_t s1 = nullptr;
    static cudaEvent_t ev_fork = nullptr, ev_join = nullptr;
    if (s1 == nullptr) {
        cudaStreamCreateWithFlags(&s1, cudaStreamNonBlocking);
        cudaEventCreateWithFlags(&ev_fork, cudaEventDisableTiming);
        cudaEventCreateWithFlags(&ev_join, cudaEventDisableTiming);
    }

    cudaFuncSetAttribute(gemm_mma_kernel, cudaFuncAttributeMaxDynamicSharedMemorySize, GEMM_SMEM);

    // 1) convert runs ALONE at full HBM bandwidth
    convert_kernel<<<2048, 256>>>(features, W);

    // 2) fork: phrase mean on side stream, hidden under the (DRAM-idle) GEMM
    cudaEventRecord(ev_fork, 0);
    cudaStreamWaitEvent(s1, ev_fork, 0);
    phrase_mean_kernel<<<M_DIM, 256, 0, s1>>>(phrases, lens, out);
    cudaEventRecord(ev_join, s1);

    // 3) GEMM on main stream
    dim3 grid(N_DIM / 64, M_DIM / 128);   // (16, 25) = 400 CTAs, 1 wave @ 4 CTAs/SM
    gemm_mma_kernel<<<grid, 128, GEMM_SMEM>>>(bias, out);

    // 4) join
    cudaStreamWaitEvent(0, ev_join, 0);
}